// round 10
// baseline (speedup 1.0000x reference)
#include <cuda_runtime.h>
#include <cstdint>

#define KDIM 7168
#define ODIM 16384
#define MDIM 32
#define OTILE 32
#define KTILE 64
#define NKT (KDIM / KTILE)     /* 112 */
#define NSC  56                /* scale cols (128-wide k blocks) */
#define NTHREADS 128           /* 4 warps = 2 ks-halves x 2 row-warps */
#define STRIDE 68              /* 64 + 4 pad floats; 68 mod 32 = 4 -> bank 4g+c, conflict-free */
#define W_STAGE_F (OTILE * STRIDE)   /* 2176 floats = 8704 B */
#define X_STAGE_F (MDIM * STRIDE)    /* 2176 floats = 8704 B */
#define NSTAGE 3

// smem: 3 * (8704 + 8704) = 52,224 B per CTA -> 4 CTAs/SM
#define SMEM_FLOATS (NSTAGE * (W_STAGE_F + X_STAGE_F))

// pre-rounded tf32 x (0.92 MB device scratch; allowed)
__device__ uint32_t g_xtf[MDIM * KDIM];

__device__ __forceinline__ uint32_t smem_u32(const void* p) {
    uint32_t a;
    asm("{ .reg .u64 t; cvta.to.shared.u64 t, %1; cvt.u32.u64 %0, t; }" : "=r"(a) : "l"(p));
    return a;
}

__device__ __forceinline__ uint32_t tf32r(float v) {   // fp32 -> tf32 round-to-nearest
    uint32_t u;
    asm("cvt.rna.tf32.f32 %0, %1;" : "=r"(u) : "f"(v));
    return u;
}

__device__ __forceinline__ void cp_async16(uint32_t dst_smem, const void* src) {
    asm volatile("cp.async.cg.shared.global [%0], [%1], 16;" :: "r"(dst_smem), "l"(src) : "memory");
}
#define CP_COMMIT() asm volatile("cp.async.commit_group;" ::: "memory")
#define CP_WAIT1()  asm volatile("cp.async.wait_group 1;" ::: "memory")

#define MMA_TF32(acc, a0, a1, a2, a3, b0, b1)                                  \
    asm volatile(                                                              \
        "mma.sync.aligned.m16n8k8.row.col.f32.tf32.tf32.f32 "                  \
        "{%0,%1,%2,%3}, {%4,%5,%6,%7}, {%8,%9}, {%0,%1,%2,%3};"                \
        : "+f"((acc)[0]), "+f"((acc)[1]), "+f"((acc)[2]), "+f"((acc)[3])       \
        : "r"(a0), "r"(a1), "r"(a2), "r"(a3), "r"(b0), "r"(b1))

// ---- prologue kernel: round x to tf32 once ----
__global__ void round_x_kernel(const float* __restrict__ X) {
    int i = blockIdx.x * blockDim.x + threadIdx.x;
    if (i < MDIM * KDIM) g_xtf[i] = tf32r(X[i]);
}

__global__ __launch_bounds__(NTHREADS, 4)
void linear_tf32_mma(const float* __restrict__ W,
                     const float* __restrict__ S, float* __restrict__ out)
{
    extern __shared__ float smem[];
    float*    wbuf = smem;                                       // 3 W stages
    uint32_t* xbuf = reinterpret_cast<uint32_t*>(smem + NSTAGE * W_STAGE_F);

    const int tid  = threadIdx.x;
    const int lane = tid & 31;
    const int w    = tid >> 5;          // 0..3
    const int q    = w >> 1;            // ks-half (0,1): owns ks [q*4, q*4+4) of 8
    const int wrow = w & 1;             // row-warp: o rows [wrow*16, wrow*16+16)
    const int bx   = blockIdx.x;
    const int o_base = bx * OTILE;
    const int srow = bx >> 2;           // scale blocks are 128 o-rows, OTILE=32

    const int g = lane >> 2;   // 0..7
    const int c = lane & 3;    // 0..3

    float acc[4][4];
    #pragma unroll
    for (int i = 0; i < 4; i++)
        #pragma unroll
        for (int j = 0; j < 4; j++) acc[i][j] = 0.0f;

    const uint32_t wsm = smem_u32(wbuf);
    const uint32_t xsm = smem_u32(xbuf);
    const uint32_t* xtf = g_xtf;

    // ---- tile loader: W 32x64 (512 chunks, 4/thread), X 32x64 (512 chunks, 4/thread)
    #define ISSUE_TILE(kt_, st_) do {                                                    \
        const uint32_t wd = wsm + (uint32_t)(st_) * (W_STAGE_F * 4);                     \
        const uint32_t xd = xsm + (uint32_t)(st_) * (X_STAGE_F * 4);                     \
        const float* gw = W + (size_t)o_base * KDIM + (size_t)(kt_) * KTILE;             \
        const uint32_t* gx = xtf + (size_t)(kt_) * KTILE;                                \
        _Pragma("unroll")                                                                \
        for (int i_ = 0; i_ < 4; i_++) {                                                 \
            int idx_ = i_ * NTHREADS + tid;                                              \
            int row_ = idx_ >> 4, col_ = idx_ & 15;                                      \
            cp_async16(wd + (uint32_t)(row_ * STRIDE + col_ * 4) * 4u,                   \
                       gw + (size_t)row_ * KDIM + (size_t)col_ * 4);                     \
        }                                                                                \
        _Pragma("unroll")                                                                \
        for (int i_ = 0; i_ < 4; i_++) {                                                 \
            int idx_ = i_ * NTHREADS + tid;                                              \
            int row_ = idx_ >> 4, col_ = idx_ & 15;                                      \
            cp_async16(xd + (uint32_t)(row_ * STRIDE + col_ * 4) * 4u,                   \
                       gx + (size_t)row_ * KDIM + (size_t)col_ * 4);                     \
        }                                                                                \
    } while (0)

    // prologue: tiles 0,1 in flight (groups 0,1)
    ISSUE_TILE(0, 0); CP_COMMIT();
    ISSUE_TILE(1, 1); CP_COMMIT();

    #pragma unroll 1
    for (int kt = 0; kt < NKT; kt++) {
        CP_WAIT1();            // groups 0..kt done -> tile kt resident
        __syncthreads();       // publish fills; all warps done reading slot (kt+2)%3 at kt-1

        // issue tile kt+2 into the slot freed at iteration kt-1 (group kt+2)
        if (kt + 2 < NKT) {
            ISSUE_TILE(kt + 2, (kt + 2) % 3);
        }
        CP_COMMIT();           // empty groups keep group == tile numbering aligned

        const float s = S[(size_t)srow * NSC + (kt >> 1)];

        const float*    wstage = wbuf + (kt % 3) * W_STAGE_F;
        const uint32_t* xstage = xbuf + (kt % 3) * X_STAGE_F;
        const int r0 = wrow * 16 + g;

        #pragma unroll
        for (int ks = 0; ks < 4; ks++) {
            const int k0 = q * 32 + ks * 8;

            uint32_t a0 = tf32r(s * wstage[ r0      * STRIDE + k0 + c    ]);
            uint32_t a1 = tf32r(s * wstage[(r0 + 8) * STRIDE + k0 + c    ]);
            uint32_t a2 = tf32r(s * wstage[ r0      * STRIDE + k0 + c + 4]);
            uint32_t a3 = tf32r(s * wstage[(r0 + 8) * STRIDE + k0 + c + 4]);

            #pragma unroll
            for (int mt = 0; mt < 4; mt++) {
                uint32_t b0 = xstage[(mt * 8 + g) * STRIDE + k0 + c];
                uint32_t b1 = xstage[(mt * 8 + g) * STRIDE + k0 + 4 + c];
                MMA_TF32(acc[mt], a0, a1, a2, a3, b0, b1);
            }
        }
        // no trailing barrier: next iteration's top barrier protects slot reuse
    }

    // ---- epilogue: reduce the 2 ks-halves, then store ----
    __syncthreads();                                 // all MMA reads of wbuf done
    float4* red = reinterpret_cast<float4*>(wbuf);   // 4 KB scratch in retired wbuf
    if (q == 1) {
        #pragma unroll
        for (int mt = 0; mt < 4; mt++)
            red[(wrow * 4 + mt) * 32 + lane] =
                make_float4(acc[mt][0], acc[mt][1], acc[mt][2], acc[mt][3]);
    }
    __syncthreads();

    if (q == 0) {
        const int o0 = o_base + wrow * 16 + g;
        #pragma unroll
        for (int mt = 0; mt < 4; mt++) {
            float4 v = red[(wrow * 4 + mt) * 32 + lane];
            const int m0 = mt * 8 + c * 2;
            // d0:(g,2c) d1:(g,2c+1) d2:(g+8,2c) d3:(g+8,2c+1); rows=o, cols=m
            out[(size_t)m0       * ODIM + o0    ] = acc[mt][0] + v.x;
            out[(size_t)(m0 + 1) * ODIM + o0    ] = acc[mt][1] + v.y;
            out[(size_t)m0       * ODIM + o0 + 8] = acc[mt][2] + v.z;
            out[(size_t)(m0 + 1) * ODIM + o0 + 8] = acc[mt][3] + v.w;
        }
    }
}

extern "C" void kernel_launch(void* const* d_in, const int* in_sizes, int n_in,
                              void* d_out, int out_size) {
    const float* x = (const float*)d_in[0];
    const float* w = (const float*)d_in[1];
    const float* s = (const float*)d_in[2];
    float* out = (float*)d_out;

    round_x_kernel<<<(MDIM * KDIM + 511) / 512, 512>>>(x);

    const size_t smem_bytes = SMEM_FLOATS * sizeof(float);
    cudaFuncSetAttribute(linear_tf32_mma,
                         cudaFuncAttributeMaxDynamicSharedMemorySize, (int)smem_bytes);
    linear_tf32_mma<<<ODIM / OTILE, NTHREADS, smem_bytes>>>(w, s, out);
}

// round 11
// speedup vs baseline: 1.2357x; 1.2357x over previous
#include <cuda_runtime.h>
#include <cstdint>

#define KDIM 7168
#define ODIM 16384
#define MDIM 32
#define OTILE 64
#define KTILE 64
#define NKT_TOTAL (KDIM / KTILE)   /* 112 */
#define KSPLIT 2
#define NKT_HALF (NKT_TOTAL / KSPLIT)  /* 56 tiles per CTA */
#define NSC  56                 /* scale cols (128-wide k blocks) */
#define NTHREADS 128            /* 4 warps = 2 ks-halves x 2 row-warps */
#define STRIDE 68               /* 64+4 pad; 68 mod 32 = 4 -> bank 4g+c, conflict-free */
#define W_STAGE_F (OTILE * STRIDE)   /* 4352 floats = 17,408 B */
#define X_STAGE_F (MDIM * STRIDE)    /* 2176 floats =  8,704 B */
#define NSTAGE 2

// smem: 2 * (17408 + 8704) = 52,224 B per CTA -> 4 CTAs/SM (regs: 128thr x <=112 x 4 < 64K)
#define SMEM_FLOATS (NSTAGE * (W_STAGE_F + X_STAGE_F))

__device__ uint32_t g_xtf[MDIM * KDIM];                 // pre-rounded tf32 x (0.92 MB)
__device__ float    g_part[KSPLIT * MDIM * ODIM];       // k-split partials (4 MB)

__device__ __forceinline__ uint32_t smem_u32(const void* p) {
    uint32_t a;
    asm("{ .reg .u64 t; cvta.to.shared.u64 t, %1; cvt.u32.u64 %0, t; }" : "=r"(a) : "l"(p));
    return a;
}

__device__ __forceinline__ uint32_t tf32r(float v) {    // fp32 -> tf32 round-to-nearest
    uint32_t u;
    asm("cvt.rna.tf32.f32 %0, %1;" : "=r"(u) : "f"(v));
    return u;
}

__device__ __forceinline__ void cp_async16(uint32_t dst_smem, const void* src) {
    asm volatile("cp.async.cg.shared.global [%0], [%1], 16;" :: "r"(dst_smem), "l"(src) : "memory");
}
#define CP_COMMIT() asm volatile("cp.async.commit_group;" ::: "memory")
#define CP_WAIT0()  asm volatile("cp.async.wait_group 0;" ::: "memory")

#define MMA_TF32(acc, a0, a1, a2, a3, b0, b1)                                  \
    asm volatile(                                                              \
        "mma.sync.aligned.m16n8k8.row.col.f32.tf32.tf32.f32 "                  \
        "{%0,%1,%2,%3}, {%4,%5,%6,%7}, {%8,%9}, {%0,%1,%2,%3};"                \
        : "+f"((acc)[0]), "+f"((acc)[1]), "+f"((acc)[2]), "+f"((acc)[3])       \
        : "r"(a0), "r"(a1), "r"(a2), "r"(a3), "r"(b0), "r"(b1))

// ---- prologue: round x to tf32 once ----
__global__ void round_x_kernel(const float* __restrict__ X) {
    int i = blockIdx.x * blockDim.x + threadIdx.x;
    if (i < MDIM * KDIM) g_xtf[i] = tf32r(X[i]);
}

// ---- epilogue: sum the two k-half partials ----
__global__ void reduce_kernel(float* __restrict__ out) {
    int i = blockIdx.x * blockDim.x + threadIdx.x;      // float4 index
    const float4* p = reinterpret_cast<const float4*>(g_part);
    float4 a = p[i];
    float4 b = p[i + (MDIM * ODIM) / 4];
    reinterpret_cast<float4*>(out)[i] =
        make_float4(a.x + b.x, a.y + b.y, a.z + b.z, a.w + b.w);
}

__global__ __launch_bounds__(NTHREADS, 4)
void linear_tf32_mma(const float* __restrict__ W, const float* __restrict__ S)
{
    extern __shared__ float smem[];
    float*    wbuf = smem;                                       // 2 W stages
    uint32_t* xbuf = reinterpret_cast<uint32_t*>(smem + NSTAGE * W_STAGE_F);

    const int tid  = threadIdx.x;
    const int lane = tid & 31;
    const int w    = tid >> 5;          // 0..3
    const int q    = w >> 1;            // ks-half of the 64-wide tile (0,1)
    const int wrow = w & 1;             // row-warp: o rows [wrow*32, wrow*32+32)
    const int ob   = blockIdx.x >> 1;   // o-block (0..255)
    const int kh   = blockIdx.x & 1;    // k-half (0,1)
    const int o_base = ob * OTILE;
    const int srow = ob >> 1;           // scale blocks are 128 o-rows
    const int kt0  = kh * NKT_HALF;     // first tile of this CTA's k-range

    const int g = lane >> 2;   // 0..7
    const int c = lane & 3;    // 0..3

    // acc[blk][mt][4]: blk = o-row block (rows wrow*32 + blk*16 + g(+8))
    float acc[2][4][4];
    #pragma unroll
    for (int b = 0; b < 2; b++)
        #pragma unroll
        for (int i = 0; i < 4; i++)
            #pragma unroll
            for (int j = 0; j < 4; j++) acc[b][i][j] = 0.0f;

    const uint32_t wsm = smem_u32(wbuf);
    const uint32_t xsm = smem_u32(xbuf);
    const uint32_t* xtf = g_xtf;

    // ---- tile loader: W 64x64 (1024 chunks, 8/thread), X 32x64 (512 chunks, 4/thread)
    #define ISSUE_TILE(kt_, st_) do {                                                    \
        const uint32_t wd = wsm + (uint32_t)(st_) * (W_STAGE_F * 4);                     \
        const uint32_t xd = xsm + (uint32_t)(st_) * (X_STAGE_F * 4);                     \
        const float* gw = W + (size_t)o_base * KDIM + (size_t)(kt_) * KTILE;             \
        const uint32_t* gx = xtf + (size_t)(kt_) * KTILE;                                \
        _Pragma("unroll")                                                                \
        for (int i_ = 0; i_ < 8; i_++) {                                                 \
            int idx_ = i_ * NTHREADS + tid;                                              \
            int row_ = idx_ >> 4, col_ = idx_ & 15;                                      \
            cp_async16(wd + (uint32_t)(row_ * STRIDE + col_ * 4) * 4u,                   \
                       gw + (size_t)row_ * KDIM + (size_t)col_ * 4);                     \
        }                                                                                \
        _Pragma("unroll")                                                                \
        for (int i_ = 0; i_ < 4; i_++) {                                                 \
            int idx_ = i_ * NTHREADS + tid;                                              \
            int row_ = idx_ >> 4, col_ = idx_ & 15;                                      \
            cp_async16(xd + (uint32_t)(row_ * STRIDE + col_ * 4) * 4u,                   \
                       gx + (size_t)row_ * KDIM + (size_t)col_ * 4);                     \
        }                                                                                \
    } while (0)

    ISSUE_TILE(kt0, 0); CP_COMMIT();

    #pragma unroll 1
    for (int it = 0; it < NKT_HALF; it++) {
        const int kt = kt0 + it;

        CP_WAIT0();            // tile kt resident (group issued at it-1 or prologue)
        __syncthreads();       // publish fills; all warps done reading slot (it-1)&1

        if (it + 1 < NKT_HALF) {
            ISSUE_TILE(kt + 1, (it + 1) & 1);    // overlaps compute of tile kt
        }
        CP_COMMIT();

        const float s = S[(size_t)srow * NSC + (kt >> 1)];

        const float*    wstage = wbuf + (it & 1) * W_STAGE_F;
        const uint32_t* xstage = xbuf + (it & 1) * X_STAGE_F;
        const int r0 = wrow * 32 + g;

        #pragma unroll
        for (int ks = 0; ks < 4; ks++) {
            const int k0 = q * 32 + ks * 8;

            uint32_t a[2][4];
            #pragma unroll
            for (int b = 0; b < 2; b++) {
                const int r = r0 + b * 16;
                a[b][0] = tf32r(s * wstage[ r      * STRIDE + k0 + c    ]);
                a[b][1] = tf32r(s * wstage[(r + 8) * STRIDE + k0 + c    ]);
                a[b][2] = tf32r(s * wstage[ r      * STRIDE + k0 + c + 4]);
                a[b][3] = tf32r(s * wstage[(r + 8) * STRIDE + k0 + c + 4]);
            }

            #pragma unroll
            for (int mt = 0; mt < 4; mt++) {
                uint32_t b0 = xstage[(mt * 8 + g) * STRIDE + k0 + c];
                uint32_t b1 = xstage[(mt * 8 + g) * STRIDE + k0 + 4 + c];
                MMA_TF32(acc[0][mt], a[0][0], a[0][1], a[0][2], a[0][3], b0, b1);
                MMA_TF32(acc[1][mt], a[1][0], a[1][1], a[1][2], a[1][3], b0, b1);
            }
        }
        // next iteration's top barrier protects slot reuse
    }

    // ---- CTA-internal reduce of the 2 ks-halves, then write k-half partial ----
    __syncthreads();
    float4* red = reinterpret_cast<float4*>(wbuf);   // 2*2*4*32*16B = 8 KB scratch
    if (q == 1) {
        #pragma unroll
        for (int b = 0; b < 2; b++)
            #pragma unroll
            for (int mt = 0; mt < 4; mt++)
                red[((wrow * 2 + b) * 4 + mt) * 32 + lane] =
                    make_float4(acc[b][mt][0], acc[b][mt][1], acc[b][mt][2], acc[b][mt][3]);
    }
    __syncthreads();

    if (q == 0) {
        float* part = g_part + (size_t)kh * MDIM * ODIM;
        #pragma unroll
        for (int b = 0; b < 2; b++) {
            const int o0 = o_base + wrow * 32 + b * 16 + g;
            #pragma unroll
            for (int mt = 0; mt < 4; mt++) {
                float4 v = red[((wrow * 2 + b) * 4 + mt) * 32 + lane];
                const int m0 = mt * 8 + c * 2;
                // d0:(g,2c) d1:(g,2c+1) d2:(g+8,2c) d3:(g+8,2c+1); rows=o, cols=m
                part[(size_t)m0       * ODIM + o0    ] = acc[0 + b * 0][0][0] * 0.0f + acc[b][mt][0] + v.x;
                part[(size_t)(m0 + 1) * ODIM + o0    ] = acc[b][mt][1] + v.y;
                part[(size_t)m0       * ODIM + o0 + 8] = acc[b][mt][2] + v.z;
                part[(size_t)(m0 + 1) * ODIM + o0 + 8] = acc[b][mt][3] + v.w;
            }
        }
    }
}

extern "C" void kernel_launch(void* const* d_in, const int* in_sizes, int n_in,
                              void* d_out, int out_size) {
    const float* x = (const float*)d_in[0];
    const float* w = (const float*)d_in[1];
    const float* s = (const float*)d_in[2];
    float* out = (float*)d_out;

    round_x_kernel<<<(MDIM * KDIM + 511) / 512, 512>>>(x);

    const size_t smem_bytes = SMEM_FLOATS * sizeof(float);
    cudaFuncSetAttribute(linear_tf32_mma,
                         cudaFuncAttributeMaxDynamicSharedMemorySize, (int)smem_bytes);
    linear_tf32_mma<<<(ODIM / OTILE) * KSPLIT, NTHREADS, smem_bytes>>>(w, s);

    reduce_kernel<<<(MDIM * ODIM / 4) / 256, 256>>>(out);
}